// round 1
// baseline (speedup 1.0000x reference)
#include <cuda_runtime.h>

#define LSEQ 768
#define NSEQ 256
#define MD   256
#define MSAD 23
#define SEQD 22
#define ZD   128
#define NB   14
#define RC   32

// Scratch (allocation-free per harness rules)
__device__ float g_sp[LSEQ * MD];   // s + pos2 + bs + bpos2 + bmsa, per l
__device__ float g_sq[LSEQ * ZD];   // seq@Wq + bq
__device__ float g_kb[LSEQ * ZD];   // seq@Wk + bk + bpos

// ---------------------------------------------------------------------------
// Precompute all per-position row vectors. One block per l, 256 threads.
// ---------------------------------------------------------------------------
__global__ __launch_bounds__(256) void precompute(
    const float* __restrict__ seq,
    const float* __restrict__ Ws,   const float* __restrict__ bs,
    const float* __restrict__ Wq,   const float* __restrict__ bq,
    const float* __restrict__ Wk,   const float* __restrict__ bk,
    const float* __restrict__ bpos,
    const float* __restrict__ Wpos2,const float* __restrict__ bpos2,
    const float* __restrict__ bmsa)
{
    const int l = blockIdx.x;
    const int c = threadIdx.x;

    __shared__ float srow[SEQD];
    if (c < SEQD) srow[c] = seq[l * SEQD + c];
    __syncthreads();

    // sp[l, c] : seq@Ws + bits(l)@Wpos2 + biases
    float acc = bs[c] + bpos2[c] + bmsa[c];
    #pragma unroll
    for (int d = 0; d < SEQD; d++) acc += srow[d] * Ws[d * MD + c];
    #pragma unroll
    for (int b = 0; b < NB; b++)
        if ((l >> b) & 1) acc += Wpos2[b * MD + c];
    g_sp[l * MD + c] = acc;

    if (c < ZD) {
        float aq = bq[c];
        float ak = bk[c] + bpos[c];
        #pragma unroll
        for (int d = 0; d < SEQD; d++) {
            const float sv = srow[d];
            aq += sv * Wq[d * ZD + c];
            ak += sv * Wk[d * ZD + c];
        }
        g_sq[l * ZD + c] = aq;
        g_kb[l * ZD + c] = ak;
    }
}

// ---------------------------------------------------------------------------
// m[n,l,:] = msa[n,l,:] @ Wmsa + g_sp[l,:]
// 4 rows per block, 64 threads/row, float4 per thread. Wmsa in smem.
// ---------------------------------------------------------------------------
__global__ __launch_bounds__(256) void mkern(
    const float* __restrict__ msa,
    const float* __restrict__ Wmsa,
    float* __restrict__ outm)
{
    __shared__ float Wsh[MSAD][MD];
    __shared__ float rowsh[4][MSAD + 1];

    const int tid = threadIdx.x;
    for (int i = tid; i < MSAD * MD; i += 256)
        Wsh[i / MD][i % MD] = Wmsa[i];

    const long base_row = (long)blockIdx.x * 4;
    if (tid < 4 * MSAD) {
        const int rr = tid / MSAD, k = tid % MSAD;
        rowsh[rr][k] = msa[(base_row + rr) * MSAD + k];
    }
    __syncthreads();

    const int  rr  = tid >> 6;          // 0..3 row within block
    const int  c   = (tid & 63) * 4;    // channel base
    const long row = base_row + rr;
    const int  l   = (int)(row % LSEQ);

    float4 acc = *reinterpret_cast<const float4*>(&g_sp[l * MD + c]);
    #pragma unroll
    for (int k = 0; k < MSAD; k++) {
        const float  mv = rowsh[rr][k];
        const float4 w  = *reinterpret_cast<const float4*>(&Wsh[k][c]);
        acc.x += mv * w.x; acc.y += mv * w.y;
        acc.z += mv * w.z; acc.w += mv * w.w;
    }
    *reinterpret_cast<float4*>(&outm[row * MD + c]) = acc;
}

// ---------------------------------------------------------------------------
// z[i,j,:] = g_sq[j,:] + g_kb[i,:] + Wpos[clamp(j-i,-32,32)+32,:]
// Block: fixed i, 8 j's, 32 threads/j, float4 each.
// ---------------------------------------------------------------------------
__global__ __launch_bounds__(256) void zkern(
    const float* __restrict__ Wpos,
    float* __restrict__ outz)
{
    const int i   = blockIdx.y;
    const int tid = threadIdx.x;
    const int jl  = tid >> 5;           // 0..7
    const int j   = blockIdx.x * 8 + jl;
    const int c   = (tid & 31) * 4;

    __shared__ float kb[ZD];
    if (tid < 32)
        *reinterpret_cast<float4*>(&kb[tid * 4]) =
            *reinterpret_cast<const float4*>(&g_kb[i * ZD + tid * 4]);
    __syncthreads();

    int rel = j - i;
    rel = min(max(rel, -RC), RC) + RC;

    const float4 q  = *reinterpret_cast<const float4*>(&g_sq[j * ZD + c]);
    const float4 k4 = *reinterpret_cast<const float4*>(&kb[c]);
    const float4 w  = *reinterpret_cast<const float4*>(&Wpos[rel * ZD + c]);

    float4 o;
    o.x = q.x + k4.x + w.x;
    o.y = q.y + k4.y + w.y;
    o.z = q.z + k4.z + w.z;
    o.w = q.w + k4.w + w.w;

    const long off = ((long)i * LSEQ + j) * ZD + c;
    *reinterpret_cast<float4*>(&outz[off]) = o;
}

// ---------------------------------------------------------------------------
extern "C" void kernel_launch(void* const* d_in, const int* in_sizes, int n_in,
                              void* d_out, int out_size)
{
    const float* seq   = (const float*)d_in[0];
    const float* msa   = (const float*)d_in[1];
    const float* Wmsa  = (const float*)d_in[2];
    const float* bmsa  = (const float*)d_in[3];
    const float* Ws    = (const float*)d_in[4];
    const float* bs    = (const float*)d_in[5];
    const float* Wq    = (const float*)d_in[6];
    const float* bq    = (const float*)d_in[7];
    const float* Wk    = (const float*)d_in[8];
    const float* bk    = (const float*)d_in[9];
    const float* Wpos  = (const float*)d_in[10];
    const float* bpos  = (const float*)d_in[11];
    const float* Wpos2 = (const float*)d_in[12];
    const float* bpos2 = (const float*)d_in[13];

    float* outm = (float*)d_out;
    float* outz = outm + (long)NSEQ * LSEQ * MD;

    precompute<<<LSEQ, 256>>>(seq, Ws, bs, Wq, bq, Wk, bk, bpos, Wpos2, bpos2, bmsa);
    mkern<<<(NSEQ * LSEQ) / 4, 256>>>(msa, Wmsa, outm);
    zkern<<<dim3(LSEQ / 8, LSEQ), 256>>>(Wpos, outz);
}

// round 2
// speedup vs baseline: 2.8384x; 2.8384x over previous
#include <cuda_runtime.h>

#define LSEQ 768
#define NSEQ 256
#define MD   256
#define MSAD 23
#define SEQD 22
#define ZD   128
#define NB   14
#define RC   32

// Only scratch needed: kb[i,:] = seq@Wk + bk + bpos  (384 KB)
__device__ float g_kb[LSEQ * ZD];

// ---- packed f32x2 helpers (sm_103a FFMA2 path, PTX-only per SASS_QUICKREF) ----
__device__ __forceinline__ unsigned long long pk2(float a, float b) {
    unsigned long long r;
    asm("mov.b64 %0, {%1, %2};" : "=l"(r) : "f"(a), "f"(b));
    return r;
}
__device__ __forceinline__ unsigned long long dup2(float a) {
    unsigned long long r;
    asm("mov.b64 %0, {%1, %1};" : "=l"(r) : "f"(a));
    return r;
}
__device__ __forceinline__ void upk2(unsigned long long v, float& a, float& b) {
    asm("mov.b64 {%0, %1}, %2;" : "=f"(a), "=f"(b) : "l"(v));
}
__device__ __forceinline__ unsigned long long fma2(unsigned long long a,
                                                   unsigned long long b,
                                                   unsigned long long c) {
    unsigned long long d;
    asm("fma.rn.f32x2 %0, %1, %2, %3;" : "=l"(d) : "l"(a), "l"(b), "l"(c));
    return d;
}

__device__ __forceinline__ float4 ld4(const float* p) {
    return *reinterpret_cast<const float4*>(p);
}

// ---------------------------------------------------------------------------
// kb[i,c] = seq[i]@Wk[:,c] + bk[c] + bpos[c].  2 rows per 256-thread block.
// ---------------------------------------------------------------------------
__global__ __launch_bounds__(256) void kbkern(
    const float* __restrict__ seq, const float* __restrict__ Wk,
    const float* __restrict__ bk,  const float* __restrict__ bpos)
{
    const int tid = threadIdx.x;
    const int rr  = tid >> 7;            // 0..1
    const int c   = tid & 127;
    const int i   = blockIdx.x * 2 + rr;

    __shared__ float s[2][SEQD];
    if (tid < 2 * SEQD)
        s[tid / SEQD][tid % SEQD] = seq[(blockIdx.x * 2 + tid / SEQD) * SEQD + tid % SEQD];
    __syncthreads();

    float a = bk[c] + bpos[c];
    #pragma unroll
    for (int d = 0; d < SEQD; d++) a += s[rr][d] * Wk[d * ZD + c];
    g_kb[i * ZD + c] = a;
}

// ---------------------------------------------------------------------------
// Fused main kernel: 1152 blocks of 128 threads.
//   blockIdx % 3 in {0,1} -> m-path (one block per l, 768 blocks)
//   blockIdx % 3 == 2     -> z-path (j-tile of 4, half of i, 384 blocks)
// ---------------------------------------------------------------------------
__global__ __launch_bounds__(128, 3) void mainkern(
    const float* __restrict__ seq,  const float* __restrict__ msa,
    const float* __restrict__ Wmsa, const float* __restrict__ bmsa,
    const float* __restrict__ Ws,   const float* __restrict__ bs,
    const float* __restrict__ Wq,   const float* __restrict__ bq,
    const float* __restrict__ Wpos, const float* __restrict__ Wpos2,
    const float* __restrict__ bpos2,
    float* __restrict__ outm, float* __restrict__ outz)
{
    const int b   = blockIdx.x;
    const int tid = threadIdx.x;
    const int sel = b % 3;

    if (sel == 2) {
        // ----------------- z-path: z[i,j,:] = sq[j] + kb[i] + Wpos[rel] -----
        const int zid   = b / 3;          // 0..383
        const int jt    = zid >> 1;       // 0..191
        const int ihalf = zid & 1;
        const int j     = jt * 4 + (tid >> 5);
        const int c     = (tid & 31) * 4;

        // sq[j, c..c+3] inline (one-time, 22 FMA x4)
        float4 q;
        q.x = bq[c]; q.y = bq[c + 1]; q.z = bq[c + 2]; q.w = bq[c + 3];
        #pragma unroll
        for (int d = 0; d < SEQD; d++) {
            const float  sv = seq[j * SEQD + d];
            const float4 w  = ld4(Wq + d * ZD + c);
            q.x += sv * w.x; q.y += sv * w.y; q.z += sv * w.z; q.w += sv * w.w;
        }

        const int i0 = ihalf * (LSEQ / 2);
        for (int i = i0; i < i0 + LSEQ / 2; i++) {
            const float4 kb = __ldg(reinterpret_cast<const float4*>(&g_kb[i * ZD + c]));
            int rel = j - i;
            rel = min(max(rel, -RC), RC) + RC;
            const float4 wp = ld4(Wpos + rel * ZD + c);
            float4 o;
            o.x = q.x + kb.x + wp.x;
            o.y = q.y + kb.y + wp.y;
            o.z = q.z + kb.z + wp.z;
            o.w = q.w + kb.w + wp.w;
            __stcs(reinterpret_cast<float4*>(&outz[((long)i * LSEQ + j) * ZD + c]), o);
        }
        return;
    }

    // -------------------- m-path: m[n,l,:] = msa[n,l,:]@Wmsa + sp[l,:] ------
    const int l  = (b / 3) * 2 + sel;     // 0..767
    const int rg = tid >> 6;              // 0..1: row subgroup
    const int c  = (tid & 63) * 4;        // channel base

    __shared__ float rowsh[NSEQ * 24];    // msa column, padded rows (24 KB)
    __shared__ float srow[SEQD];

    if (tid < SEQD) srow[tid] = seq[l * SEQD + tid];
    for (int idx = tid; idx < NSEQ * MSAD; idx += 128) {
        const int n = idx / MSAD;
        const int k = idx - n * MSAD;
        rowsh[n * 24 + k] = msa[(n * LSEQ + l) * MSAD + k];
    }
    // zero the pad lane so float4 smem reads are safe
    for (int n = tid; n < NSEQ; n += 128) rowsh[n * 24 + 23] = 0.0f;
    __syncthreads();

    // weights for this thread's 4 channels, packed as f32x2 pairs (regs)
    unsigned long long w0[MSAD], w1[MSAD];
    #pragma unroll
    for (int k = 0; k < MSAD; k++) {
        const float4 w = ld4(Wmsa + k * MD + c);
        w0[k] = pk2(w.x, w.y);
        w1[k] = pk2(w.z, w.w);
    }

    // sp[l, c..c+3] inline
    float4 sp;
    sp.x = bs[c]     + bpos2[c]     + bmsa[c];
    sp.y = bs[c + 1] + bpos2[c + 1] + bmsa[c + 1];
    sp.z = bs[c + 2] + bpos2[c + 2] + bmsa[c + 2];
    sp.w = bs[c + 3] + bpos2[c + 3] + bmsa[c + 3];
    #pragma unroll
    for (int d = 0; d < SEQD; d++) {
        const float  sv = srow[d];
        const float4 w  = ld4(Ws + d * MD + c);
        sp.x += sv * w.x; sp.y += sv * w.y; sp.z += sv * w.z; sp.w += sv * w.w;
    }
    #pragma unroll
    for (int bb = 0; bb < NB; bb++)
        if ((l >> bb) & 1) {
            const float4 w = ld4(Wpos2 + bb * MD + c);
            sp.x += w.x; sp.y += w.y; sp.z += w.z; sp.w += w.w;
        }
    const unsigned long long sp01 = pk2(sp.x, sp.y);
    const unsigned long long sp23 = pk2(sp.z, sp.w);

    // main loop over n: 2 rows per iteration (rg selects)
    for (int it = 0; it < NSEQ / 2; it++) {
        const int n = it * 2 + rg;
        const float4* r4 = reinterpret_cast<const float4*>(&rowsh[n * 24]);
        float mv[24];
        *reinterpret_cast<float4*>(&mv[0])  = r4[0];
        *reinterpret_cast<float4*>(&mv[4])  = r4[1];
        *reinterpret_cast<float4*>(&mv[8])  = r4[2];
        *reinterpret_cast<float4*>(&mv[12]) = r4[3];
        *reinterpret_cast<float4*>(&mv[16]) = r4[4];
        *reinterpret_cast<float4*>(&mv[20]) = r4[5];

        unsigned long long a01 = sp01, a23 = sp23;
        #pragma unroll
        for (int k = 0; k < MSAD; k++) {
            const unsigned long long p = dup2(mv[k]);
            a01 = fma2(w0[k], p, a01);
            a23 = fma2(w1[k], p, a23);
        }
        float4 o;
        upk2(a01, o.x, o.y);
        upk2(a23, o.z, o.w);
        __stcs(reinterpret_cast<float4*>(&outm[((long)n * LSEQ + l) * MD + c]), o);
    }
}

// ---------------------------------------------------------------------------
extern "C" void kernel_launch(void* const* d_in, const int* in_sizes, int n_in,
                              void* d_out, int out_size)
{
    const float* seq   = (const float*)d_in[0];
    const float* msa   = (const float*)d_in[1];
    const float* Wmsa  = (const float*)d_in[2];
    const float* bmsa  = (const float*)d_in[3];
    const float* Ws    = (const float*)d_in[4];
    const float* bs    = (const float*)d_in[5];
    const float* Wq    = (const float*)d_in[6];
    const float* bq    = (const float*)d_in[7];
    const float* Wk    = (const float*)d_in[8];
    const float* bk    = (const float*)d_in[9];
    const float* Wpos  = (const float*)d_in[10];
    const float* bpos  = (const float*)d_in[11];
    const float* Wpos2 = (const float*)d_in[12];
    const float* bpos2 = (const float*)d_in[13];

    float* outm = (float*)d_out;
    float* outz = outm + (long)NSEQ * LSEQ * MD;

    kbkern<<<LSEQ / 2, 256>>>(seq, Wk, bk, bpos);
    mainkern<<<1152, 128>>>(seq, msa, Wmsa, bmsa, Ws, bs, Wq, bq,
                            Wpos, Wpos2, bpos2, outm, outz);
}